// round 14
// baseline (speedup 1.0000x reference)
#include <cuda_runtime.h>
#include <cuda_bf16.h>
#include <cuda_fp16.h>
#include <cstdint>

#define N_NODES 100000
#define N_EDGES 1600000
#define C 64

// Scratch: fp16 transformed features h = x @ W, CSR row ptrs.
__device__ __half g_h[(size_t)N_NODES * C];
__device__ int g_row_ptr[N_NODES + 1];

// SW128 swizzle on byte offsets (rows of 128B): XOR bits[6:4] with bits[9:7].
#define SW(o) ((o) ^ (((o) >> 3) & 0x70))

static __device__ __forceinline__ uint32_t smem_u32(const void* p) {
    uint32_t a;
    asm("{ .reg .u64 t; cvta.to.shared.u64 t, %1; cvt.u32.u64 %0, t; }" : "=r"(a) : "l"(p));
    return a;
}
static __device__ __forceinline__ void ldsm_x4(uint32_t& r0, uint32_t& r1,
                                               uint32_t& r2, uint32_t& r3, uint32_t addr) {
    asm volatile("ldmatrix.sync.aligned.m8n8.x4.shared.b16 {%0,%1,%2,%3}, [%4];"
                 : "=r"(r0), "=r"(r1), "=r"(r2), "=r"(r3) : "r"(addr));
}
static __device__ __forceinline__ void ldsm_x4_t(uint32_t& r0, uint32_t& r1,
                                                 uint32_t& r2, uint32_t& r3, uint32_t addr) {
    asm volatile("ldmatrix.sync.aligned.m8n8.x4.trans.shared.b16 {%0,%1,%2,%3}, [%4];"
                 : "=r"(r0), "=r"(r1), "=r"(r2), "=r"(r3) : "r"(addr));
}
static __device__ __forceinline__ void mma16816(float* c, const uint32_t* a,
                                                uint32_t b0, uint32_t b1) {
    asm volatile(
        "mma.sync.aligned.m16n8k16.row.col.f32.f16.f16.f32 "
        "{%0,%1,%2,%3}, {%4,%5,%6,%7}, {%8,%9}, {%0,%1,%2,%3};"
        : "+f"(c[0]), "+f"(c[1]), "+f"(c[2]), "+f"(c[3])
        : "r"(a[0]), "r"(a[1]), "r"(a[2]), "r"(a[3]), "r"(b0), "r"(b1));
}

#define RP_NT    (N_EDGES / 8)                // 200000
#define RP_B     ((RP_NT + 255) / 256)        // 782
#define GEMM_B   ((N_NODES + 63) / 64)        // 1563 (64-row tiles)

// ---------------------------------------------------------------------------
// Kernel A (merged): blocks [0, RP_B) fill CSR row pointers (issue-bound);
// blocks [RP_B, RP_B+GEMM_B) compute h = (x @ W) in fp16 via HMMA with
// 64-row tiles. Unchanged from R13 (proven).
// ---------------------------------------------------------------------------
__global__ __launch_bounds__(256) void transform_kernel(const float* __restrict__ x,
                                                        const float* __restrict__ w,
                                                        const int* __restrict__ row_index) {
    __shared__ __align__(128) __half As[64 * 64];    // 8 KB x tile (fp16)
    __shared__ __align__(128) __half Ws[64 * 64];    // 8 KB W (fp16)

    if (blockIdx.x < RP_B) {
        const int t = blockIdx.x * 256 + threadIdx.x;
        if (t >= RP_NT) return;

        const int4* r4 = (const int4*)row_index;
        int4 a = __ldg(&r4[2 * t]);
        int4 b = __ldg(&r4[2 * t + 1]);

        int prev = (t == 0) ? -1 : __ldg(&row_index[8 * t - 1]);
        const bool tail = (t == RP_NT - 1);

        if (b.w == prev && !tail) return;

        int vals[8] = {a.x, a.y, a.z, a.w, b.x, b.y, b.z, b.w};
        const int ebase = 8 * t;
#pragma unroll
        for (int i = 0; i < 8; i++) {
            int cur = vals[i];
            if (cur != prev) {
                for (int n = prev + 1; n <= cur; n++) g_row_ptr[n] = ebase + i;
                prev = cur;
            }
        }
        if (tail) {
            for (int n = prev + 1; n <= N_NODES; n++) g_row_ptr[n] = N_EDGES;
        }
        return;
    }

    const int bid = blockIdx.x - RP_B;
    const int tid = threadIdx.x;
    const int wid = tid >> 5;
    const int lane = tid & 31;
    const long row0 = (long)bid * 64;

    {
        const float4* w4 = (const float4*)w;
        char* wsb = (char*)Ws;
#pragma unroll
        for (int i = 0; i < 4; i++) {
            int ch = i * 256 + tid;
            int k = ch >> 4, n4 = ch & 15;
            float4 v = __ldg(&w4[ch]);
            __half2 h0 = __floats2half2_rn(v.x, v.y);
            __half2 h1 = __floats2half2_rn(v.z, v.w);
            uint2 pk = make_uint2(*(uint32_t*)&h0, *(uint32_t*)&h1);
            *(uint2*)(wsb + SW(k * 128 + n4 * 8)) = pk;
        }
    }
    {
        const float4* x4 = (const float4*)x;
        char* asb = (char*)As;
#pragma unroll
        for (int i = 0; i < 4; i++) {
            int ch = i * 256 + tid;
            int r = ch >> 4, c4 = ch & 15;
            long gr = row0 + r;
            float4 v = make_float4(0.f, 0.f, 0.f, 0.f);
            if (gr < N_NODES) v = __ldg(&x4[gr * 16 + c4]);
            __half2 h0 = __floats2half2_rn(v.x, v.y);
            __half2 h1 = __floats2half2_rn(v.z, v.w);
            uint2 pk = make_uint2(*(uint32_t*)&h0, *(uint32_t*)&h1);
            *(uint2*)(asb + SW(r * 128 + c4 * 8)) = pk;
        }
    }
    __syncthreads();

    const uint32_t as_base = smem_u32(As);
    const uint32_t ws_base = smem_u32(Ws);
    const int rg = wid & 3;
    const int chalf = wid >> 2;
    const int lr = lane & 15;
    const int lc = lane >> 4;

    float c[4][4];
#pragma unroll
    for (int nt = 0; nt < 4; nt++)
#pragma unroll
        for (int j = 0; j < 4; j++) c[nt][j] = 0.f;

#pragma unroll
    for (int kc = 0; kc < 4; kc++) {
        uint32_t a[4];
        {
            uint32_t addr = as_base + SW((rg * 16 + lr) * 128 + kc * 32 + lc * 16);
            ldsm_x4(a[0], a[1], a[2], a[3], addr);
        }
#pragma unroll
        for (int np = 0; np < 2; np++) {
            uint32_t b0, b1, b2, b3;
            uint32_t addr = ws_base +
                SW((kc * 16 + lr) * 128 + (chalf * 32 + np * 16 + lc * 8) * 2);
            ldsm_x4_t(b0, b1, b2, b3, addr);
            mma16816(c[2 * np], a, b0, b1);
            mma16816(c[2 * np + 1], a, b2, b3);
        }
    }

    const int qr = lane >> 2;
    const int qc = (lane & 3) * 2;
    long rlo = row0 + rg * 16 + qr;
    long rhi = rlo + 8;
#pragma unroll
    for (int nt = 0; nt < 4; nt++) {
        int col = chalf * 32 + nt * 8 + qc;
        if (rlo < N_NODES) {
            __half2 h = __floats2half2_rn(c[nt][0], c[nt][1]);
            *(__half2*)(g_h + (size_t)rlo * C + col) = h;
        }
        if (rhi < N_NODES) {
            __half2 h = __floats2half2_rn(c[nt][2], c[nt][3]);
            *(__half2*)(g_h + (size_t)rhi * C + col) = h;
        }
    }
}

// ---------------------------------------------------------------------------
// Kernel B: out = segment_sum(h[col]) * deg + bias.
// fp16 gather with 32-bit byte offsets (g_h < 2^32 bytes), depth-2 A/B
// software pipeline (loads lead their reduce by a full reduce+load phase),
// fp16 pairwise tree per group, fp32 accumulation across groups.
// 16 lanes/node, 2 nodes/warp, no atomics.
// ---------------------------------------------------------------------------
__global__ __launch_bounds__(256) void agg_kernel(const int* __restrict__ column_index,
                                                  const float* __restrict__ degrees,
                                                  const float* __restrict__ bias,
                                                  float* __restrict__ out) {
    const int warp = (blockIdx.x * blockDim.x + threadIdx.x) >> 5;
    const int lane = threadIdx.x & 31;
    const int half = lane >> 4;
    const int hl = lane & 15;
    const int node = warp * 2 + half;
    if (node >= N_NODES) return;

    const char* hb = (const char*)g_h;
    const uint32_t hloff = (uint32_t)hl * 8u;

    const int start = g_row_ptr[node];
    const int end = g_row_ptr[node + 1];
    const int ng = (end - start) >> 2;   // full 4-edge groups

    float ax = 0.f, ay = 0.f, az = 0.f, aw = 0.f;

    uint2 A[4], B[4];

#define LOADG(buf, be)                                                        \
    do {                                                                      \
        int _s0 = __ldg(&column_index[(be)]);                                 \
        int _s1 = __ldg(&column_index[(be) + 1]);                             \
        int _s2 = __ldg(&column_index[(be) + 2]);                             \
        int _s3 = __ldg(&column_index[(be) + 3]);                             \
        buf[0] = __ldg((const uint2*)(hb + (((uint32_t)_s0 << 7) + hloff)));  \
        buf[1] = __ldg((const uint2*)(hb + (((uint32_t)_s1 << 7) + hloff)));  \
        buf[2] = __ldg((const uint2*)(hb + (((uint32_t)_s2 << 7) + hloff)));  \
        buf[3] = __ldg((const uint2*)(hb + (((uint32_t)_s3 << 7) + hloff)));  \
    } while (0)

#define REDUCEG(buf)                                                          \
    do {                                                                      \
        __half2 _p0 = __hadd2(*(__half2*)&buf[0].x, *(__half2*)&buf[1].x);    \
        __half2 _p1 = __hadd2(*(__half2*)&buf[0].y, *(__half2*)&buf[1].y);    \
        __half2 _q0 = __hadd2(*(__half2*)&buf[2].x, *(__half2*)&buf[3].x);    \
        __half2 _q1 = __hadd2(*(__half2*)&buf[2].y, *(__half2*)&buf[3].y);    \
        __half2 _t0 = __hadd2(_p0, _q0);                                      \
        __half2 _t1 = __hadd2(_p1, _q1);                                      \
        float2 _f0 = __half22float2(_t0);                                     \
        float2 _f1 = __half22float2(_t1);                                     \
        ax += _f0.x; ay += _f0.y; az += _f1.x; aw += _f1.y;                   \
    } while (0)

    if (ng > 0) LOADG(A, start);
    if (ng > 1) LOADG(B, start + 4);

    int g = 0;
    for (; g + 2 <= ng; g += 2) {
        REDUCEG(A);
        if (g + 2 < ng) LOADG(A, start + (g + 2) * 4);
        REDUCEG(B);
        if (g + 3 < ng) LOADG(B, start + (g + 3) * 4);
    }
    if (g < ng) REDUCEG(A);   // odd last group (held in A)

    // tail: exact fp32 path (<= 3 edges)
    for (int e = start + ng * 4; e < end; e++) {
        int s0 = __ldg(&column_index[e]);
        uint2 u = __ldg((const uint2*)(hb + (((uint32_t)s0 << 7) + hloff)));
        float2 f0 = __half22float2(*(__half2*)&u.x);
        float2 f1 = __half22float2(*(__half2*)&u.y);
        ax += f0.x; ay += f0.y; az += f1.x; aw += f1.y;
    }
#undef LOADG
#undef REDUCEG

    const float d = __ldg(&degrees[node]);
    const float4 b = __ldg((const float4*)bias + hl);
    float4 o;
    o.x = ax * d + b.x;
    o.y = ay * d + b.y;
    o.z = az * d + b.z;
    o.w = aw * d + b.w;
    ((float4*)(out + (size_t)node * C))[hl] = o;
}

// ---------------------------------------------------------------------------
extern "C" void kernel_launch(void* const* d_in, const int* in_sizes, int n_in,
                              void* d_out, int out_size) {
    const float* x            = (const float*)d_in[0];   // [N_NODES, 64]
    const float* weight       = (const float*)d_in[1];   // [64, 64]
    const float* bias         = (const float*)d_in[2];   // [64]
    const int*   column_index = (const int*)d_in[3];     // [N_EDGES]
    const int*   row_index    = (const int*)d_in[4];     // [N_EDGES] sorted
    const float* degrees      = (const float*)d_in[5];   // [N_NODES]
    float* out = (float*)d_out;                          // [N_NODES, 64]

    // A) h = x @ W (fp16, HMMA, 64-row tiles) overlapped with rowptr fill
    transform_kernel<<<RP_B + GEMM_B, 256>>>(x, weight, row_index);

    // B) out = segment_sum(h[col]) * deg + bias  (depth-2 pipelined gather)
    const int warps = (N_NODES + 1) / 2;
    agg_kernel<<<(warps * 32 + 255) / 256, 256>>>(column_index, degrees, bias, out);
}

// round 15
// speedup vs baseline: 1.1440x; 1.1440x over previous
#include <cuda_runtime.h>
#include <cuda_bf16.h>
#include <cuda_fp16.h>
#include <cstdint>

#define N_NODES 100000
#define N_EDGES 1600000
#define C 64

// Scratch: fp16 transformed features h = x @ W, CSR row ptrs.
__device__ __half g_h[(size_t)N_NODES * C];
__device__ int g_row_ptr[N_NODES + 1];

// SW128 swizzle on byte offsets (rows of 128B): XOR bits[6:4] with bits[9:7].
#define SW(o) ((o) ^ (((o) >> 3) & 0x70))

static __device__ __forceinline__ uint32_t smem_u32(const void* p) {
    uint32_t a;
    asm("{ .reg .u64 t; cvta.to.shared.u64 t, %1; cvt.u32.u64 %0, t; }" : "=r"(a) : "l"(p));
    return a;
}
static __device__ __forceinline__ void ldsm_x4(uint32_t& r0, uint32_t& r1,
                                               uint32_t& r2, uint32_t& r3, uint32_t addr) {
    asm volatile("ldmatrix.sync.aligned.m8n8.x4.shared.b16 {%0,%1,%2,%3}, [%4];"
                 : "=r"(r0), "=r"(r1), "=r"(r2), "=r"(r3) : "r"(addr));
}
static __device__ __forceinline__ void ldsm_x4_t(uint32_t& r0, uint32_t& r1,
                                                 uint32_t& r2, uint32_t& r3, uint32_t addr) {
    asm volatile("ldmatrix.sync.aligned.m8n8.x4.trans.shared.b16 {%0,%1,%2,%3}, [%4];"
                 : "=r"(r0), "=r"(r1), "=r"(r2), "=r"(r3) : "r"(addr));
}
static __device__ __forceinline__ void mma16816(float* c, const uint32_t* a,
                                                uint32_t b0, uint32_t b1) {
    asm volatile(
        "mma.sync.aligned.m16n8k16.row.col.f32.f16.f16.f32 "
        "{%0,%1,%2,%3}, {%4,%5,%6,%7}, {%8,%9}, {%0,%1,%2,%3};"
        : "+f"(c[0]), "+f"(c[1]), "+f"(c[2]), "+f"(c[3])
        : "r"(a[0]), "r"(a[1]), "r"(a[2]), "r"(a[3]), "r"(b0), "r"(b1));
}

#define RP_NT    (N_EDGES / 8)                // 200000
#define RP_B     ((RP_NT + 255) / 256)        // 782
#define GEMM_B   ((N_NODES + 63) / 64)        // 1563 (64-row tiles)

// ---------------------------------------------------------------------------
// Kernel A (merged): blocks [0, RP_B) fill CSR row pointers (issue-bound);
// blocks [RP_B, RP_B+GEMM_B) compute h = (x @ W) in fp16 via HMMA with
// 64-row tiles. Unchanged from R13 (proven).
// ---------------------------------------------------------------------------
__global__ __launch_bounds__(256) void transform_kernel(const float* __restrict__ x,
                                                        const float* __restrict__ w,
                                                        const int* __restrict__ row_index) {
    __shared__ __align__(128) __half As[64 * 64];    // 8 KB x tile (fp16)
    __shared__ __align__(128) __half Ws[64 * 64];    // 8 KB W (fp16)

    if (blockIdx.x < RP_B) {
        const int t = blockIdx.x * 256 + threadIdx.x;
        if (t >= RP_NT) return;

        const int4* r4 = (const int4*)row_index;
        int4 a = __ldg(&r4[2 * t]);
        int4 b = __ldg(&r4[2 * t + 1]);

        int prev = (t == 0) ? -1 : __ldg(&row_index[8 * t - 1]);
        const bool tail = (t == RP_NT - 1);

        if (b.w == prev && !tail) return;

        int vals[8] = {a.x, a.y, a.z, a.w, b.x, b.y, b.z, b.w};
        const int ebase = 8 * t;
#pragma unroll
        for (int i = 0; i < 8; i++) {
            int cur = vals[i];
            if (cur != prev) {
                for (int n = prev + 1; n <= cur; n++) g_row_ptr[n] = ebase + i;
                prev = cur;
            }
        }
        if (tail) {
            for (int n = prev + 1; n <= N_NODES; n++) g_row_ptr[n] = N_EDGES;
        }
        return;
    }

    const int bid = blockIdx.x - RP_B;
    const int tid = threadIdx.x;
    const int wid = tid >> 5;
    const int lane = tid & 31;
    const long row0 = (long)bid * 64;

    {
        const float4* w4 = (const float4*)w;
        char* wsb = (char*)Ws;
#pragma unroll
        for (int i = 0; i < 4; i++) {
            int ch = i * 256 + tid;
            int k = ch >> 4, n4 = ch & 15;
            float4 v = __ldg(&w4[ch]);
            __half2 h0 = __floats2half2_rn(v.x, v.y);
            __half2 h1 = __floats2half2_rn(v.z, v.w);
            uint2 pk = make_uint2(*(uint32_t*)&h0, *(uint32_t*)&h1);
            *(uint2*)(wsb + SW(k * 128 + n4 * 8)) = pk;
        }
    }
    {
        const float4* x4 = (const float4*)x;
        char* asb = (char*)As;
#pragma unroll
        for (int i = 0; i < 4; i++) {
            int ch = i * 256 + tid;
            int r = ch >> 4, c4 = ch & 15;
            long gr = row0 + r;
            float4 v = make_float4(0.f, 0.f, 0.f, 0.f);
            if (gr < N_NODES) v = __ldg(&x4[gr * 16 + c4]);
            __half2 h0 = __floats2half2_rn(v.x, v.y);
            __half2 h1 = __floats2half2_rn(v.z, v.w);
            uint2 pk = make_uint2(*(uint32_t*)&h0, *(uint32_t*)&h1);
            *(uint2*)(asb + SW(r * 128 + c4 * 8)) = pk;
        }
    }
    __syncthreads();

    const uint32_t as_base = smem_u32(As);
    const uint32_t ws_base = smem_u32(Ws);
    const int rg = wid & 3;
    const int chalf = wid >> 2;
    const int lr = lane & 15;
    const int lc = lane >> 4;

    float c[4][4];
#pragma unroll
    for (int nt = 0; nt < 4; nt++)
#pragma unroll
        for (int j = 0; j < 4; j++) c[nt][j] = 0.f;

#pragma unroll
    for (int kc = 0; kc < 4; kc++) {
        uint32_t a[4];
        {
            uint32_t addr = as_base + SW((rg * 16 + lr) * 128 + kc * 32 + lc * 16);
            ldsm_x4(a[0], a[1], a[2], a[3], addr);
        }
#pragma unroll
        for (int np = 0; np < 2; np++) {
            uint32_t b0, b1, b2, b3;
            uint32_t addr = ws_base +
                SW((kc * 16 + lr) * 128 + (chalf * 32 + np * 16 + lc * 8) * 2);
            ldsm_x4_t(b0, b1, b2, b3, addr);
            mma16816(c[2 * np], a, b0, b1);
            mma16816(c[2 * np + 1], a, b2, b3);
        }
    }

    const int qr = lane >> 2;
    const int qc = (lane & 3) * 2;
    long rlo = row0 + rg * 16 + qr;
    long rhi = rlo + 8;
#pragma unroll
    for (int nt = 0; nt < 4; nt++) {
        int col = chalf * 32 + nt * 8 + qc;
        if (rlo < N_NODES) {
            __half2 h = __floats2half2_rn(c[nt][0], c[nt][1]);
            *(__half2*)(g_h + (size_t)rlo * C + col) = h;
        }
        if (rhi < N_NODES) {
            __half2 h = __floats2half2_rn(c[nt][2], c[nt][3]);
            *(__half2*)(g_h + (size_t)rhi * C + col) = h;
        }
    }
}

// ---------------------------------------------------------------------------
// Kernel B: out = segment_sum(h[col]) * deg + bias.
// 4 nodes/warp: 8 lanes per node, uint4 (16B = 8 halves) per lane, so one
// LDG.128 instruction serves 4 edges (one per node subgroup) = 4 rows.
// Depth-2 fp16 pairwise tree per 4-edge group, fp32 accumulation across
// groups. No atomics, no explicit pipeline (occupancy provides MLP).
// ---------------------------------------------------------------------------
__global__ __launch_bounds__(256) void agg_kernel(const int* __restrict__ column_index,
                                                  const float* __restrict__ degrees,
                                                  const float* __restrict__ bias,
                                                  float* __restrict__ out) {
    const int warp = (blockIdx.x * blockDim.x + threadIdx.x) >> 5;
    const int lane = threadIdx.x & 31;
    const int q = lane >> 3;          // node slot within warp (0..3)
    const int ql = lane & 7;          // uint4 slot within 64-col row (0..7)
    const int node = warp * 4 + q;
    if (node >= N_NODES) return;

    const uint4* hrows = (const uint4*)g_h;   // 8 uint4 per node row

    const int start = g_row_ptr[node];
    const int end = g_row_ptr[node + 1];

    float a0 = 0.f, a1 = 0.f, a2 = 0.f, a3 = 0.f;
    float a4 = 0.f, a5 = 0.f, a6 = 0.f, a7 = 0.f;

    int e = start;
    // body: 4-edge groups, depth-2 fp16 tree on 8 halves, one fp32 flush
#pragma unroll 2
    for (; e + 3 < end; e += 4) {
        int s0 = __ldg(&column_index[e]);
        int s1 = __ldg(&column_index[e + 1]);
        int s2 = __ldg(&column_index[e + 2]);
        int s3 = __ldg(&column_index[e + 3]);
        uint4 u0 = __ldg(&hrows[(size_t)s0 * 8 + ql]);
        uint4 u1 = __ldg(&hrows[(size_t)s1 * 8 + ql]);
        uint4 u2 = __ldg(&hrows[(size_t)s2 * 8 + ql]);
        uint4 u3 = __ldg(&hrows[(size_t)s3 * 8 + ql]);
        // level 1
        __half2 p0 = __hadd2(*(__half2*)&u0.x, *(__half2*)&u1.x);
        __half2 p1 = __hadd2(*(__half2*)&u0.y, *(__half2*)&u1.y);
        __half2 p2 = __hadd2(*(__half2*)&u0.z, *(__half2*)&u1.z);
        __half2 p3 = __hadd2(*(__half2*)&u0.w, *(__half2*)&u1.w);
        __half2 q0 = __hadd2(*(__half2*)&u2.x, *(__half2*)&u3.x);
        __half2 q1 = __hadd2(*(__half2*)&u2.y, *(__half2*)&u3.y);
        __half2 q2 = __hadd2(*(__half2*)&u2.z, *(__half2*)&u3.z);
        __half2 q3 = __hadd2(*(__half2*)&u2.w, *(__half2*)&u3.w);
        // level 2
        __half2 t0 = __hadd2(p0, q0);
        __half2 t1 = __hadd2(p1, q1);
        __half2 t2 = __hadd2(p2, q2);
        __half2 t3 = __hadd2(p3, q3);
        // flush to fp32
        float2 f0 = __half22float2(t0);
        float2 f1 = __half22float2(t1);
        float2 f2 = __half22float2(t2);
        float2 f3 = __half22float2(t3);
        a0 += f0.x; a1 += f0.y; a2 += f1.x; a3 += f1.y;
        a4 += f2.x; a5 += f2.y; a6 += f3.x; a7 += f3.y;
    }
    // tail: exact fp32 path (<= 3 edges)
    for (; e < end; e++) {
        int s0 = __ldg(&column_index[e]);
        uint4 u = __ldg(&hrows[(size_t)s0 * 8 + ql]);
        float2 f0 = __half22float2(*(__half2*)&u.x);
        float2 f1 = __half22float2(*(__half2*)&u.y);
        float2 f2 = __half22float2(*(__half2*)&u.z);
        float2 f3 = __half22float2(*(__half2*)&u.w);
        a0 += f0.x; a1 += f0.y; a2 += f1.x; a3 += f1.y;
        a4 += f2.x; a5 += f2.y; a6 += f3.x; a7 += f3.y;
    }

    const float d = __ldg(&degrees[node]);
    const float4 b0 = __ldg((const float4*)bias + ql * 2);
    const float4 b1 = __ldg((const float4*)bias + ql * 2 + 1);
    float4 o0, o1;
    o0.x = a0 * d + b0.x;  o0.y = a1 * d + b0.y;
    o0.z = a2 * d + b0.z;  o0.w = a3 * d + b0.w;
    o1.x = a4 * d + b1.x;  o1.y = a5 * d + b1.y;
    o1.z = a6 * d + b1.z;  o1.w = a7 * d + b1.w;
    float4* orow = (float4*)(out + (size_t)node * C);
    orow[ql * 2] = o0;
    orow[ql * 2 + 1] = o1;
}

// ---------------------------------------------------------------------------
extern "C" void kernel_launch(void* const* d_in, const int* in_sizes, int n_in,
                              void* d_out, int out_size) {
    const float* x            = (const float*)d_in[0];   // [N_NODES, 64]
    const float* weight       = (const float*)d_in[1];   // [64, 64]
    const float* bias         = (const float*)d_in[2];   // [64]
    const int*   column_index = (const int*)d_in[3];     // [N_EDGES]
    const int*   row_index    = (const int*)d_in[4];     // [N_EDGES] sorted
    const float* degrees      = (const float*)d_in[5];   // [N_NODES]
    float* out = (float*)d_out;                          // [N_NODES, 64]

    // A) h = x @ W (fp16, HMMA, 64-row tiles) overlapped with rowptr fill
    transform_kernel<<<RP_B + GEMM_B, 256>>>(x, weight, row_index);

    // B) out = segment_sum(h[col]) * deg + bias  (4 nodes/warp, uint4 lanes)
    const int warps = (N_NODES + 3) / 4;
    agg_kernel<<<(warps * 32 + 255) / 256, 256>>>(column_index, degrees, bias, out);
}